// round 2
// baseline (speedup 1.0000x reference)
#include <cuda_runtime.h>
#include <cstdint>

#define NLAYERS 6
#define HDIM    256
#define BSZ     131072
#define MT      128          // samples per CTA tile
#define NTHR    256

// Pre-packed (tf32-rounded, B-fragment layout) weights for the 36 H x H GEMMs.
// mat index = ((st*6 + layer)*3 + g)   st: 0=s-net, 1=t-net   g: 0=W2,1=W3,2=W4
__device__ float g_wpack[36 * 65536];

// ---------------------------------------------------------------------------
// helpers
// ---------------------------------------------------------------------------
__device__ __forceinline__ uint32_t tf32r(float f) {
    uint32_t u;
    asm("cvt.rna.tf32.f32 %0, %1;" : "=r"(u) : "f"(f));
    return u;
}

__device__ __forceinline__ void cpasync16(uint32_t dst, const void* src) {
    asm volatile("cp.async.cg.shared.global [%0], [%1], 16;" :: "r"(dst), "l"(src));
}

__device__ __forceinline__ void mma_tf32(float acc[4],
                                         uint32_t a0, uint32_t a1, uint32_t a2, uint32_t a3,
                                         uint32_t b0, uint32_t b1) {
    asm volatile(
        "mma.sync.aligned.m16n8k8.row.col.f32.tf32.tf32.f32 "
        "{%0,%1,%2,%3}, {%4,%5,%6,%7}, {%8,%9}, {%0,%1,%2,%3};"
        : "+f"(acc[0]), "+f"(acc[1]), "+f"(acc[2]), "+f"(acc[3])
        : "r"(a0), "r"(a1), "r"(a2), "r"(a3), "r"(b0), "r"(b1));
}

struct Smem {
    float actP[32768];      // 128 x 256 activations, A-fragment-packed layout
    float wbuf[2][8192];    // double-buffered weight slab (32 k-rows each)
    float bias_s[256];
    float w5s[256];
    float xv[128][2];
    float sarr[128];
    float tarr[128];
    float ldet[128];
};

// A-fragment packed address for element (m, k) of the 128x256 activation tile.
// m16n8k8 A-frag: a0:(r,c) r=lane/4,c=lane%4; a1:r+8; a2:c+4; a3:r+8,c+4
__device__ __forceinline__ int packAddr(int m, int k) {
    int r = m & 15, c = k & 7;
    return (((k >> 3) * 8 + (m >> 4)) * 32 + (r & 7) * 4 + (c & 3)) * 4
           + ((c >> 2) * 2 + (r >> 3));
}

// ---------------------------------------------------------------------------
// prepack: round W2/W3/W4 (s & t) to tf32 and permute into B-fragment layout
// B-frag (8x8, col for row.col mma): b0:(k=lane%4, n=lane/4), b1:(k=lane%4+4, n=lane/4)
// ---------------------------------------------------------------------------
__global__ void prepack_kernel(const float* sW2, const float* sW3, const float* sW4,
                               const float* tW2, const float* tW3, const float* tW4) {
    int gid = blockIdx.x * blockDim.x + threadIdx.x;
    if (gid >= 36 * 65536) return;
    int mat = gid >> 16;
    int e   = gid & 65535;
    int k = e >> 8, n = e & 255;
    int st = mat / 18, rem = mat % 18, l = rem / 3, g = rem % 3;
    const float* src;
    int sel = st * 3 + g;
    switch (sel) {
        case 0: src = sW2; break;
        case 1: src = sW3; break;
        case 2: src = sW4; break;
        case 3: src = tW2; break;
        case 4: src = tW3; break;
        default: src = tW4; break;
    }
    float v = src[l * 65536 + e];
    int dst = mat * 65536 + ((k >> 3) * 32 + (n >> 3)) * 64
              + ((n & 7) * 4 + (k & 3)) * 2 + ((k >> 2) & 1);
    g_wpack[dst] = __uint_as_float(tf32r(v));
}

// ---------------------------------------------------------------------------
// one 128x256 @ 256x256 GEMM (+bias, relu, tf32-round), in/out = sm->actP
// warp grid 2(M) x 4(N); per-warp tile 64x64; accumulators 128 f32/thread
// ---------------------------------------------------------------------------
__device__ void gemm256(Smem* sm, const float* wmat, const float* bias_g, int tid) {
    int wid = tid >> 5, lane = tid & 31;
    int wm = wid >> 2, wn = wid & 3;

    float acc[4][8][4];
#pragma unroll
    for (int a = 0; a < 4; a++)
#pragma unroll
        for (int b = 0; b < 8; b++)
#pragma unroll
            for (int q = 0; q < 4; q++) acc[a][b][q] = 0.f;

    sm->bias_s[tid] = bias_g[tid];

    uint32_t wbase[2];
    wbase[0] = (uint32_t)__cvta_generic_to_shared(&sm->wbuf[0][0]);
    wbase[1] = (uint32_t)__cvta_generic_to_shared(&sm->wbuf[1][0]);

    // prefetch slab 0
#pragma unroll
    for (int i = 0; i < 8; i++) {
        int fo = tid * 4 + i * 1024;
        cpasync16(wbase[0] + fo * 4, wmat + fo);
    }
    asm volatile("cp.async.commit_group;");

    for (int sl = 0; sl < 8; sl++) {
        if (sl < 7) {
            uint32_t base = wbase[(sl + 1) & 1];
            const float* g = wmat + (sl + 1) * 8192;
#pragma unroll
            for (int i = 0; i < 8; i++) {
                int fo = tid * 4 + i * 1024;
                cpasync16(base + fo * 4, g + fo);
            }
            asm volatile("cp.async.commit_group;");
            asm volatile("cp.async.wait_group 1;");
        } else {
            asm volatile("cp.async.wait_group 0;");
        }
        __syncthreads();

        const float* wb = sm->wbuf[sl & 1];
#pragma unroll
        for (int ks = 0; ks < 4; ks++) {
            int kstep = sl * 4 + ks;
            uint4 a[4];
#pragma unroll
            for (int mc = 0; mc < 4; mc++)
                a[mc] = *(const uint4*)&sm->actP[((kstep * 8 + wm * 4 + mc) * 32 + lane) * 4];
            uint2 b[8];
#pragma unroll
            for (int nc = 0; nc < 8; nc++)
                b[nc] = *(const uint2*)&wb[((ks * 32 + wn * 8 + nc) * 32 + lane) * 2];
#pragma unroll
            for (int mc = 0; mc < 4; mc++)
#pragma unroll
                for (int nc = 0; nc < 8; nc++)
                    mma_tf32(acc[mc][nc], a[mc].x, a[mc].y, a[mc].z, a[mc].w,
                             b[nc].x, b[nc].y);
        }
        __syncthreads();
    }

    // epilogue: bias + relu + tf32-round, write back in A-frag layout
#pragma unroll
    for (int mc = 0; mc < 4; mc++) {
#pragma unroll
        for (int nc = 0; nc < 8; nc++) {
            int m0 = wm * 64 + mc * 16 + (lane >> 2);
            int n0 = wn * 64 + nc * 8 + (lane & 3) * 2;
            float bx = sm->bias_s[n0], by = sm->bias_s[n0 + 1];
            float v00 = fmaxf(acc[mc][nc][0] + bx, 0.f);
            float v01 = fmaxf(acc[mc][nc][1] + by, 0.f);
            float v10 = fmaxf(acc[mc][nc][2] + bx, 0.f);
            float v11 = fmaxf(acc[mc][nc][3] + by, 0.f);
            sm->actP[packAddr(m0,     n0    )] = __uint_as_float(tf32r(v00));
            sm->actP[packAddr(m0,     n0 + 1)] = __uint_as_float(tf32r(v01));
            sm->actP[packAddr(m0 + 8, n0    )] = __uint_as_float(tf32r(v10));
            sm->actP[packAddr(m0 + 8, n0 + 1)] = __uint_as_float(tf32r(v11));
        }
    }
    __syncthreads();
}

// first layer: h = relu(x[c] * W1[c,:] + B1)  (outer product, fp32, tf32-round on store)
__device__ void layer0(Smem* sm, const float* w1row, const float* b1, int c, int tid) {
    int n4 = (tid & 63) * 4;
    int mbase = (tid >> 6) * 32;
    float4 w  = *(const float4*)&w1row[n4];
    float4 bb = *(const float4*)&b1[n4];
#pragma unroll 4
    for (int mm = 0; mm < 32; mm++) {
        int m = mbase + mm;
        float xc = sm->xv[m][c];
        sm->actP[packAddr(m, n4 + 0)] = __uint_as_float(tf32r(fmaxf(fmaf(xc, w.x, bb.x), 0.f)));
        sm->actP[packAddr(m, n4 + 1)] = __uint_as_float(tf32r(fmaxf(fmaf(xc, w.y, bb.y), 0.f)));
        sm->actP[packAddr(m, n4 + 2)] = __uint_as_float(tf32r(fmaxf(fmaf(xc, w.z, bb.z), 0.f)));
        sm->actP[packAddr(m, n4 + 3)] = __uint_as_float(tf32r(fmaxf(fmaf(xc, w.w, bb.w), 0.f)));
    }
    __syncthreads();
}

// final layer: o[m] = act[m,:] . W5[:,other] + B5[other]; s = tanh(o) or t = o
__device__ void dotW5(Smem* sm, const float* w5col, float b5, bool is_s, int tid) {
    sm->w5s[tid] = w5col[tid * 2];
    __syncthreads();
    int m = tid >> 1, half = tid & 1;
    float acc = 0.f;
    int k0 = half * 128;
#pragma unroll 8
    for (int kk = 0; kk < 128; kk++) {
        int k = k0 + kk;
        acc = fmaf(sm->actP[packAddr(m, k)], sm->w5s[k], acc);
    }
    acc += __shfl_xor_sync(0xffffffffu, acc, 1);
    if (half == 0) {
        float o = acc + b5;
        if (is_s) sm->sarr[m] = tanhf(o);
        else      sm->tarr[m] = o;
    }
    __syncthreads();
}

// ---------------------------------------------------------------------------
// fused RealNVP kernel: one CTA = 128 samples through all 6 layers
// ---------------------------------------------------------------------------
__global__ void __launch_bounds__(NTHR, 1)
realnvp_kernel(const float* __restrict__ X,
               const float* __restrict__ sW1, const float* __restrict__ sB1,
               const float* __restrict__ sB2, const float* __restrict__ sB3,
               const float* __restrict__ sB4, const float* __restrict__ sW5,
               const float* __restrict__ sB5,
               const float* __restrict__ tW1, const float* __restrict__ tB1,
               const float* __restrict__ tB2, const float* __restrict__ tB3,
               const float* __restrict__ tB4, const float* __restrict__ tW5,
               const float* __restrict__ tB5,
               float* __restrict__ out) {
    extern __shared__ char smem_raw[];
    Smem* sm = (Smem*)smem_raw;
    int tid = threadIdx.x;
    int gbase = blockIdx.x * MT;

    if (tid < 128) {
        int g = gbase + tid;
        float2 xx = *(const float2*)&X[g * 2];
        sm->xv[tid][0] = logf(xx.x / (1.f - xx.x));   // logit
        sm->xv[tid][1] = logf(xx.y / (1.f - xx.y));
        sm->ldet[tid] = 0.f;
    }
    __syncthreads();

    for (int i = NLAYERS - 1; i >= 0; i--) {
        int c = (i & 1) ? 0 : 1;     // masks alternate [0,1],[1,0],... kept dim
        int other = 1 - c;

        // ---- s net ----
        layer0(sm, sW1 + i * 512 + c * 256, sB1 + i * 256, c, tid);
        gemm256(sm, g_wpack + (size_t)((0 * 6 + i) * 3 + 0) * 65536, sB2 + i * 256, tid);
        gemm256(sm, g_wpack + (size_t)((0 * 6 + i) * 3 + 1) * 65536, sB3 + i * 256, tid);
        gemm256(sm, g_wpack + (size_t)((0 * 6 + i) * 3 + 2) * 65536, sB4 + i * 256, tid);
        dotW5(sm, sW5 + i * 512 + other, sB5[i * 2 + other], true, tid);

        // ---- t net ----
        layer0(sm, tW1 + i * 512 + c * 256, tB1 + i * 256, c, tid);
        gemm256(sm, g_wpack + (size_t)((1 * 6 + i) * 3 + 0) * 65536, tB2 + i * 256, tid);
        gemm256(sm, g_wpack + (size_t)((1 * 6 + i) * 3 + 1) * 65536, tB3 + i * 256, tid);
        gemm256(sm, g_wpack + (size_t)((1 * 6 + i) * 3 + 2) * 65536, tB4 + i * 256, tid);
        dotW5(sm, tW5 + i * 512 + other, tB5[i * 2 + other], false, tid);

        // ---- coupling update ----
        if (tid < 128) {
            float sv = sm->sarr[tid], tv = sm->tarr[tid];
            sm->xv[tid][other] = (sm->xv[tid][other] - tv) * expf(-sv);
            sm->ldet[tid] -= sv;
        }
        __syncthreads();
    }

    if (tid < 128) {
        int g = gbase + tid;
        float2 o;
        o.x = 1.f / (1.f + expf(-sm->xv[tid][0]));    // sigmoid
        o.y = 1.f / (1.f + expf(-sm->xv[tid][1]));
        *(float2*)&out[g * 2] = o;
        out[2 * BSZ + g] = sm->ldet[tid];
    }
}

// ---------------------------------------------------------------------------
extern "C" void kernel_launch(void* const* d_in, const int* in_sizes, int n_in,
                              void* d_out, int out_size) {
    const float* X   = (const float*)d_in[0];
    const float* sW1 = (const float*)d_in[1];
    const float* sB1 = (const float*)d_in[2];
    const float* sW2 = (const float*)d_in[3];
    const float* sB2 = (const float*)d_in[4];
    const float* sW3 = (const float*)d_in[5];
    const float* sB3 = (const float*)d_in[6];
    const float* sW4 = (const float*)d_in[7];
    const float* sB4 = (const float*)d_in[8];
    const float* sW5 = (const float*)d_in[9];
    const float* sB5 = (const float*)d_in[10];
    const float* tW1 = (const float*)d_in[11];
    const float* tB1 = (const float*)d_in[12];
    const float* tW2 = (const float*)d_in[13];
    const float* tB2 = (const float*)d_in[14];
    const float* tW3 = (const float*)d_in[15];
    const float* tB3 = (const float*)d_in[16];
    const float* tW4 = (const float*)d_in[17];
    const float* tB4 = (const float*)d_in[18];
    const float* tW5 = (const float*)d_in[19];
    const float* tB5 = (const float*)d_in[20];

    cudaFuncSetAttribute(realnvp_kernel, cudaFuncAttributeMaxDynamicSharedMemorySize,
                         (int)sizeof(Smem));

    prepack_kernel<<<(36 * 65536) / NTHR, NTHR>>>(sW2, sW3, sW4, tW2, tW3, tW4);
    realnvp_kernel<<<BSZ / MT, NTHR, sizeof(Smem)>>>(
        X, sW1, sB1, sB2, sB3, sB4, sW5, sB5,
        tW1, tB1, tB2, tB3, tB4, tW5, tB5, (float*)d_out);
}

// round 4
// speedup vs baseline: 1.3677x; 1.3677x over previous
#include <cuda_runtime.h>
#include <cstdint>

#define NTHR 256
#define MT 128
#define BSZ 131072
#define NMAT 36
#define TOTAL_SLABS 288      // 36 mats x 8 slabs (K=32 each)
#define SLAB_FLOATS 8192
#define SLAB_BYTES 32768
#define ACT_STRIDE 136       // 136 mod 32 = 8 -> conflict-free column access

// smem byte offsets
#define OFF_WBUF 0                       // 2 x 32KB
#define OFF_ACT  65536                   // 256 x 136 x 4 = 139264
#define OFF_BIAS 204800
#define OFF_W1S  205824
#define OFF_B1S  206848
#define OFF_W5S  207872
#define OFF_XV   208896                  // 128 x 2 floats
#define OFF_PP   209920                  // 2 x 128 floats
#define OFF_SARR 210944
#define OFF_TARR 211456
#define SMEM_DYN 211968

__device__ float g_wpack[NMAT * 65536];

// ---------------------------------------------------------------------------
__device__ __forceinline__ uint32_t tf32r(float f) {
    uint32_t u; asm("cvt.rna.tf32.f32 %0, %1;" : "=r"(u) : "f"(f)); return u;
}
__device__ __forceinline__ void cpasync16(uint32_t dst, const void* src) {
    asm volatile("cp.async.cg.shared.global [%0], [%1], 16;" :: "r"(dst), "l"(src));
}
__device__ __forceinline__ void mma_tf32(float acc[4],
                                         uint32_t a0, uint32_t a1, uint32_t a2, uint32_t a3,
                                         uint32_t b0, uint32_t b1) {
    asm volatile(
        "mma.sync.aligned.m16n8k8.row.col.f32.tf32.tf32.f32 "
        "{%0,%1,%2,%3}, {%4,%5,%6,%7}, {%8,%9}, {%0,%1,%2,%3};"
        : "+f"(acc[0]), "+f"(acc[1]), "+f"(acc[2]), "+f"(acc[3])
        : "r"(a0), "r"(a1), "r"(a2), "r"(a3), "r"(b0), "r"(b1));
}

// ---------------------------------------------------------------------------
// prepack: W[k][n] -> tf32, A-fragment order for mma (A[m=n][k] = W[k][n]).
// frag id = ks*16 + mt (ks = kstep in slab, mt = n>>4); per frag 32 lanes x uint4.
// lane = (n&7)*4 + (k&3); slot = ((k>>2)&1)*2 + ((n>>3)&1)
// ---------------------------------------------------------------------------
__global__ void prepack_kernel(const float* sW2, const float* sW3, const float* sW4,
                               const float* tW2, const float* tW3, const float* tW4) {
    int gid = blockIdx.x * blockDim.x + threadIdx.x;
    if (gid >= NMAT * 65536) return;
    int mat = gid >> 16;
    int e   = gid & 65535;
    int k = e >> 8, n = e & 255;
    int st = mat / 18, rem = mat % 18, l = rem / 3, g = rem % 3;
    const float* src;
    switch (st * 3 + g) {
        case 0: src = sW2; break;
        case 1: src = sW3; break;
        case 2: src = sW4; break;
        case 3: src = tW2; break;
        case 4: src = tW3; break;
        default: src = tW4; break;
    }
    float v = src[l * 65536 + e];
    int slab = k >> 5, ks = (k >> 3) & 3, mt = n >> 4;
    int lane = (n & 7) * 4 + (k & 3);
    int slot = ((k >> 2) & 1) * 2 + ((n >> 3) & 1);
    int dst  = mat * 65536 + slab * SLAB_FLOATS + ((ks * 16 + mt) * 32 + lane) * 4 + slot;
    g_wpack[dst] = __uint_as_float(tf32r(v));
}

// ---------------------------------------------------------------------------
__global__ void __launch_bounds__(NTHR, 1)
realnvp_kernel(const float* __restrict__ X,
               const float* __restrict__ sW1, const float* __restrict__ sB1,
               const float* __restrict__ sB2, const float* __restrict__ sB3,
               const float* __restrict__ sB4, const float* __restrict__ sW5,
               const float* __restrict__ sB5,
               const float* __restrict__ tW1, const float* __restrict__ tB1,
               const float* __restrict__ tB2, const float* __restrict__ tB3,
               const float* __restrict__ tB4, const float* __restrict__ tW5,
               const float* __restrict__ tB5,
               float* __restrict__ out) {
    extern __shared__ char base[];
    float*    actf   = (float*)(base + OFF_ACT);
    uint32_t* actu   = (uint32_t*)actf;
    float*    bias_s = (float*)(base + OFF_BIAS);
    float*    w1s    = (float*)(base + OFF_W1S);
    float*    b1s    = (float*)(base + OFF_B1S);
    float*    w5s    = (float*)(base + OFF_W5S);
    float*    xv     = (float*)(base + OFF_XV);
    float*    pp     = (float*)(base + OFF_PP);
    float*    sarr   = (float*)(base + OFF_SARR);
    float*    tarr   = (float*)(base + OFF_TARR);
    uint32_t  wbuf_sh = (uint32_t)__cvta_generic_to_shared(base + OFF_WBUF);

    int tid  = threadIdx.x;
    int wid  = tid >> 5, lane = tid & 31;
    int wm   = wid >> 1;          // 0..3 feature tiles of 64
    int wn   = wid & 1;           // 0..1 sample tiles of 64
    int gbase = blockIdx.x * MT;

    float ldet = 0.f;
    if (tid < 128) {
        float2 xx = *(const float2*)&X[(gbase + tid) * 2];
        xv[tid * 2 + 0] = logf(xx.x / (1.f - xx.x));
        xv[tid * 2 + 1] = logf(xx.y / (1.f - xx.y));
    }

    // ---- weight slab prefetch (2-buffer ring) ----
    auto prefetch = [&](int q) {
        int qq = (q >= TOTAL_SLABS) ? q - TOTAL_SLABS : q;
        int j = qq >> 3, sl = qq & 7;
        int li = 5 - j / 6;
        int r6 = j % 6;
        int mat = ((r6 / 3) * 6 + li) * 3 + (r6 % 3);
        const float* src = g_wpack + (size_t)mat * 65536 + sl * SLAB_FLOATS + tid * 4;
        uint32_t dst = wbuf_sh + (uint32_t)(q & 1) * SLAB_BYTES + tid * 16;
#pragma unroll
        for (int it = 0; it < 8; it++)
            cpasync16(dst + it * 4096, src + it * 1024);
        asm volatile("cp.async.commit_group;");
    };

    prefetch(0);

    // ---- layer0: act[h][s] = relu(x[s]*W1[h] + B1[h]), tf32-rounded ----
    auto layer0 = [&](const float* w1row, const float* b1, int cdim) {
        w1s[tid] = w1row[tid];
        b1s[tid] = b1[tid];
        __syncthreads();
        int s4 = (tid & 31) * 4;
        int kb = (tid >> 5) * 32;
        float x0 = xv[(s4 + 0) * 2 + cdim], x1 = xv[(s4 + 1) * 2 + cdim];
        float x2 = xv[(s4 + 2) * 2 + cdim], x3 = xv[(s4 + 3) * 2 + cdim];
#pragma unroll 4
        for (int i = 0; i < 32; i++) {
            int k = kb + i;
            float w = w1s[k], b = b1s[k];
            uint4 v;
            v.x = tf32r(fmaxf(fmaf(x0, w, b), 0.f));
            v.y = tf32r(fmaxf(fmaf(x1, w, b), 0.f));
            v.z = tf32r(fmaxf(fmaf(x2, w, b), 0.f));
            v.w = tf32r(fmaxf(fmaf(x3, w, b), 0.f));
            *(uint4*)&actu[k * ACT_STRIDE + s4] = v;
        }
        __syncthreads();
    };

    // ---- one 256x256 GEMM over act + fused bias/relu/tf32 epilogue ----
    auto gemm = [&](int gc, const float* bias) {
        bias_s[tid] = bias[tid];
        float acc[4][8][4];
#pragma unroll
        for (int a = 0; a < 4; a++)
#pragma unroll
            for (int b = 0; b < 8; b++)
#pragma unroll
                for (int q = 0; q < 4; q++) acc[a][b][q] = 0.f;

        const uint32_t* actu_b = actu + wn * 64 + (lane >> 2);

        for (int sl = 0; sl < 8; sl++) {
            int q = gc * 8 + sl;
            __syncthreads();                 // buffer-reuse + act-ready safety
            prefetch(q + 1);
            asm volatile("cp.async.wait_group 1;");
            __syncthreads();                 // slab q visible to all threads
            const float* wb = (const float*)(base + OFF_WBUF + (q & 1) * SLAB_BYTES);
#pragma unroll
            for (int ks = 0; ks < 4; ks++) {
                uint4 a[4];
#pragma unroll
                for (int mf = 0; mf < 4; mf++)
                    a[mf] = *(const uint4*)&wb[((ks * 16 + wm * 4 + mf) * 32 + lane) * 4];
                int kk = sl * 32 + ks * 8 + (lane & 3);
                const uint32_t* p0 = actu_b + kk * ACT_STRIDE;
                const uint32_t* p1 = p0 + 4 * ACT_STRIDE;
                uint32_t b0[8], b1[8];
#pragma unroll
                for (int nf = 0; nf < 8; nf++) { b0[nf] = p0[nf * 8]; b1[nf] = p1[nf * 8]; }
#pragma unroll
                for (int mf = 0; mf < 4; mf++)
#pragma unroll
                    for (int nf = 0; nf < 8; nf++)
                        mma_tf32(acc[mf][nf], a[mf].x, a[mf].y, a[mf].z, a[mf].w,
                                 b0[nf], b1[nf]);
            }
        }
        __syncthreads();                     // all reads of act done before overwrite

        // epilogue: bias + relu + tf32, vectorized STS.64, in-place into act
#pragma unroll
        for (int mf = 0; mf < 4; mf++) {
            int f0 = wm * 64 + mf * 16 + (lane >> 2);
            float bx = bias_s[f0], by = bias_s[f0 + 8];
#pragma unroll
            for (int nf = 0; nf < 8; nf++) {
                int s0 = wn * 64 + nf * 8 + (lane & 3) * 2;
                uint2 lo, hi;
                lo.x = tf32r(fmaxf(acc[mf][nf][0] + bx, 0.f));
                lo.y = tf32r(fmaxf(acc[mf][nf][1] + bx, 0.f));
                hi.x = tf32r(fmaxf(acc[mf][nf][2] + by, 0.f));
                hi.y = tf32r(fmaxf(acc[mf][nf][3] + by, 0.f));
                *(uint2*)&actu[f0 * ACT_STRIDE + s0]       = lo;
                *(uint2*)&actu[(f0 + 8) * ACT_STRIDE + s0] = hi;
            }
        }
        __syncthreads();
    };

    // ---- final dot: o[s] = act[:, s] . W5[:, other] + B5 ----
    auto dotW5 = [&](const float* w5col, float b5, bool is_s) {
        w5s[tid] = w5col[tid * 2];
        __syncthreads();
        int s = tid & 127, part = tid >> 7;
        int k0 = part * 128;
        const float* col = actf + s;
        float a0 = 0.f, a1 = 0.f;
#pragma unroll 8
        for (int kk = 0; kk < 128; kk += 2) {
            a0 = fmaf(col[(k0 + kk) * ACT_STRIDE],     w5s[k0 + kk],     a0);
            a1 = fmaf(col[(k0 + kk + 1) * ACT_STRIDE], w5s[k0 + kk + 1], a1);
        }
        pp[part * 128 + s] = a0 + a1;
        __syncthreads();
        if (tid < 128) {
            float o = pp[tid] + pp[128 + tid] + b5;
            if (is_s) sarr[tid] = tanhf(o);
            else      tarr[tid] = o;
        }
        __syncthreads();
    };

    // ---- main flow: 6 coupling layers, reversed ----
    int gc = 0;
    for (int i = 5; i >= 0; i--) {
        int cdim = (i & 1) ? 0 : 1;
        int other = 1 - cdim;

        layer0(sW1 + i * 512 + cdim * 256, sB1 + i * 256, cdim);
        gemm(gc++, sB2 + i * 256);
        gemm(gc++, sB3 + i * 256);
        gemm(gc++, sB4 + i * 256);
        dotW5(sW5 + i * 512 + other, sB5[i * 2 + other], true);

        layer0(tW1 + i * 512 + cdim * 256, tB1 + i * 256, cdim);
        gemm(gc++, tB2 + i * 256);
        gemm(gc++, tB3 + i * 256);
        gemm(gc++, tB4 + i * 256);
        dotW5(tW5 + i * 512 + other, tB5[i * 2 + other], false);

        if (tid < 128) {
            float sv = sarr[tid], tv = tarr[tid];
            xv[tid * 2 + other] = (xv[tid * 2 + other] - tv) * expf(-sv);
            ldet -= sv;
        }
        __syncthreads();
    }

    if (tid < 128) {
        int g = gbase + tid;
        float2 o;
        o.x = 1.f / (1.f + expf(-xv[tid * 2 + 0]));
        o.y = 1.f / (1.f + expf(-xv[tid * 2 + 1]));
        *(float2*)&out[g * 2] = o;
        out[2 * BSZ + g] = ldet;
    }
    asm volatile("cp.async.wait_group 0;");
}

// ---------------------------------------------------------------------------
extern "C" void kernel_launch(void* const* d_in, const int* in_sizes, int n_in,
                              void* d_out, int out_size) {
    const float* X   = (const float*)d_in[0];
    const float* sW1 = (const float*)d_in[1];
    const float* sB1 = (const float*)d_in[2];
    const float* sW2 = (const float*)d_in[3];
    const float* sB2 = (const float*)d_in[4];
    const float* sW3 = (const float*)d_in[5];
    const float* sB3 = (const float*)d_in[6];
    const float* sW4 = (const float*)d_in[7];
    const float* sB4 = (const float*)d_in[8];
    const float* sW5 = (const float*)d_in[9];
    const float* sB5 = (const float*)d_in[10];
    const float* tW1 = (const float*)d_in[11];
    const float* tB1 = (const float*)d_in[12];
    const float* tW2 = (const float*)d_in[13];
    const float* tB2 = (const float*)d_in[14];
    const float* tW3 = (const float*)d_in[15];
    const float* tB3 = (const float*)d_in[16];
    const float* tW4 = (const float*)d_in[17];
    const float* tB4 = (const float*)d_in[18];
    const float* tW5 = (const float*)d_in[19];
    const float* tB5 = (const float*)d_in[20];

    cudaFuncSetAttribute(realnvp_kernel, cudaFuncAttributeMaxDynamicSharedMemorySize,
                         SMEM_DYN);

    prepack_kernel<<<(NMAT * 65536) / NTHR, NTHR>>>(sW2, sW3, sW4, tW2, tW3, tW4);
    realnvp_kernel<<<BSZ / MT, NTHR, SMEM_DYN>>>(
        X, sW1, sB1, sB2, sB3, sB4, sW5, sB5,
        tW1, tB1, tB2, tB3, tB4, tW5, tB5, (float*)d_out);
}